// round 15
// baseline (speedup 1.0000x reference)
#include <cuda_runtime.h>
#include <cuda_bf16.h>
#include <math.h>
#include <stdint.h>

#define B_  16
#define N_  1024
#define FIN 128
#define FO  64
#define ALPHA_ 0.2f

// Scratch (device globals: no allocation allowed)
__device__ float2   g_hs[B_ * 16 * 2048];     // tf32 h, B-fragment order, 4 MB
__device__ float2   g_pq1[B_ * N_];           // {exp(s1), exp(a*s1)}
__device__ float2   g_pq2[B_ * N_];           // {exp(s2), exp(a*s2)}
__device__ uint32_t g_bits[B_ * N_ * 32];     // adj bitmask [b][row][word], 2 MB

__device__ __forceinline__ float to_tf32(float x) {
    float r;
    asm("cvt.rna.tf32.f32 %0, %1;" : "=f"(r) : "f"(x));
    return r;
}
__device__ __forceinline__ void mma_tf32(float* d, const uint32_t* a,
                                         uint32_t b0, uint32_t b1) {
    asm volatile(
        "mma.sync.aligned.m16n8k8.row.col.f32.tf32.tf32.f32 "
        "{%0,%1,%2,%3}, {%4,%5,%6,%7}, {%8,%9}, {%0,%1,%2,%3};"
        : "+f"(d[0]), "+f"(d[1]), "+f"(d[2]), "+f"(d[3])
        : "r"(a[0]), "r"(a[1]), "r"(a[2]), "r"(a[3]), "r"(b0), "r"(b1));
}
__device__ __forceinline__ uint32_t smem_u32(const void* p) {
    uint32_t a;
    asm("{ .reg .u64 t; cvta.to.shared.u64 t, %1; cvt.u32.u64 %0, t; }"
        : "=r"(a) : "l"(p));
    return a;
}
#define CP_ASYNC16(dst_u32, src_ptr) \
    asm volatile("cp.async.cg.shared.global [%0], [%1], 16;" \
                 :: "r"(dst_u32), "l"(src_ptr))
#define CP_COMMIT() asm volatile("cp.async.commit_group;" ::: "memory")
#define CP_WAIT0()  asm volatile("cp.async.wait_group 0;" ::: "memory")

// k_attn smem layout (bytes). accbuf[64][72] (18432 B) overlays HS0+HS1.
#define HS0_OFF   0          // float2 hs[2048] = 16384
#define HS1_OFF   16384
#define SBITS_OFF 32768      // uint32 sbits[64][36] = 9216
#define PQ2_OFF   41984      // float2 pq2s[1024] = 8192
#define ZP_OFF    50176      // float zp[2][64] = 512
#define ZS_OFF    50688      // float zs[64] = 256
#define SMEM_ATTN 50944

#define SMEM_HG   66048      // sI 32K + sW 32K + sA 512 (sT reuses sI)

// ---------------------------------------------------------------------------
// Kernel 1 (fused): blocks x<16: h = inp@W -> g_hs + scores;
//                   blocks x>=16: pack adj -> g_bits (DRAM-bound, overlaps).
// ---------------------------------------------------------------------------
__global__ __launch_bounds__(256) void k_h_gemm(const float* __restrict__ inp,
                                                const float* __restrict__ W,
                                                const float* __restrict__ a,
                                                const int* __restrict__ adj) {
    extern __shared__ char sm1[];
    const int b  = blockIdx.y;
    const int t  = threadIdx.x;

    if (blockIdx.x >= 16) {
        // ---- adj packing: 8 warps, 1 row/warp, rows px*8..px*8+7 ----
        const int px   = blockIdx.x - 16;       // 0..127
        const int wid  = t >> 5;
        const int lane = t & 31;
        const int row  = px * 8 + wid;
        const int* ap = adj + (size_t)b * N_ * N_ + (size_t)row * N_ + lane;
        uint32_t* bp = g_bits + ((size_t)b * N_ + row) * 32;
#pragma unroll
        for (int wo = 0; wo < 4; wo++) {
            int va[8];
#pragma unroll
            for (int j = 0; j < 8; j++) va[j] = ap[(wo * 8 + j) * 32];
#pragma unroll
            for (int j = 0; j < 8; j++) {
                const uint32_t msk = __ballot_sync(0xffffffffu, va[j] > 0);
                if (lane == 0) bp[wo * 8 + j] = msk;
            }
        }
        return;
    }

    // ---- h-gemm part ----
    float* sI = (float*)sm1;             // [64][128]
    float* sW = (float*)(sm1 + 32768);   // [128][64]
    float* sA = (float*)(sm1 + 65536);   // [128]
    float* sT = (float*)sm1;             // [64][68] transpose stage (reuses sI)

    const int bx   = blockIdx.x;         // tile index (64 rows per tile)
    const int row0 = bx * 64;

#pragma unroll
    for (int k = 0; k < 8; k++)
        ((float4*)sW)[t + k * 256] = ((const float4*)W)[t + k * 256];
    const float4* ip = (const float4*)(inp + ((size_t)b * N_ + row0) * FIN);
#pragma unroll
    for (int k = 0; k < 8; k++)
        ((float4*)sI)[t + k * 256] = ip[t + k * 256];
    if (t < 128) sA[t] = a[t];
    __syncthreads();

    const int ot = t & 15;
    const int rt = t >> 4;
    const int lane = t & 31;

    float acc[4][4];
#pragma unroll
    for (int r = 0; r < 4; r++)
#pragma unroll
        for (int c = 0; c < 4; c++) acc[r][c] = 0.f;

#pragma unroll 4
    for (int k = 0; k < FIN; k++) {
        const float4 w4 = *(const float4*)(sW + k * FO + ot * 4);
#pragma unroll
        for (int r = 0; r < 4; r++) {
            const float iv = sI[(rt * 4 + r) * FIN + k];
            acc[r][0] += iv * w4.x;
            acc[r][1] += iv * w4.y;
            acc[r][2] += iv * w4.z;
            acc[r][3] += iv * w4.w;
        }
    }

    // fused scores (uses acc before staging)
    float s1p[4], s2p[4];
#pragma unroll
    for (int r = 0; r < 4; r++) {
        float v1 = 0.f, v2 = 0.f;
#pragma unroll
        for (int c = 0; c < 4; c++) {
            v1 += acc[r][c] * sA[ot * 4 + c];
            v2 += acc[r][c] * sA[64 + ot * 4 + c];
        }
        s1p[r] = v1; s2p[r] = v2;
    }
#pragma unroll
    for (int off = 8; off > 0; off >>= 1) {
#pragma unroll
        for (int r = 0; r < 4; r++) {
            s1p[r] += __shfl_xor_sync(0xffffffffu, s1p[r], off);
            s2p[r] += __shfl_xor_sync(0xffffffffu, s2p[r], off);
        }
    }

    // stage tf32 h into sT (stride 68), then write fragment-ordered g_hs
    __syncthreads();   // done reading sI
#pragma unroll
    for (int r = 0; r < 4; r++) {
        float4 wq;
        wq.x = to_tf32(acc[r][0]);
        wq.y = to_tf32(acc[r][1]);
        wq.z = to_tf32(acc[r][2]);
        wq.w = to_tf32(acc[r][3]);
        *(float4*)(sT + (rt * 4 + r) * 68 + ot * 4) = wq;
    }
    __syncthreads();

    {
        float2* dst = g_hs + (size_t)(b * 16 + bx) * 2048;
#pragma unroll
        for (int q = 0; q < 8; q++) {
            const int f   = q * 256 + t;
            const int l   = f & 31;
            const int blk = f >> 5;          // koct*8 + nf
            const int j0  = (blk >> 3) * 8 + (l & 3);
            const int c   = (blk & 7) * 8 + (l >> 2);
            float2 v;
            v.x = sT[j0 * 68 + c];
            v.y = sT[(j0 + 4) * 68 + c];
            dst[f] = v;
        }
    }

    if ((lane & 15) == 0) {
#pragma unroll
        for (int r = 0; r < 4; r++) {
            const int gi = b * N_ + row0 + rt * 4 + r;
            g_pq1[gi] = make_float2(__expf(s1p[r]), __expf(ALPHA_ * s1p[r]));
            g_pq2[gi] = make_float2(__expf(s2p[r]), __expf(ALPHA_ * s2p[r]));
        }
    }
}

// ---------------------------------------------------------------------------
// Kernel 2: attention via mma.sync tf32; A generated in registers from
// PRE-PACKED bitmasks (smem-resident, loaded once), B staged pre-fragmented.
// CTA: 64 i x 64 o, 512 thr, 16 warps = 4m x 2n x 2k,
// warp tile 16m x 32n x 32k, acc 16 regs -> 2 CTAs/SM.
// ---------------------------------------------------------------------------
__global__ __launch_bounds__(512, 2) void k_attn(float* __restrict__ out) {
    extern __shared__ char sm[];
    uint32_t* sbits = (uint32_t*)(sm + SBITS_OFF);  // [64][36]
    float2*   pq2s = (float2*)(sm + PQ2_OFF);
    float*    zp   = (float*)(sm + ZP_OFF);     // [2][64]
    float*    zs   = (float*)(sm + ZS_OFF);     // [64]
    float*    accbuf = (float*)sm;              // [64][72] (reuse after loop)
    const uint32_t smbase = smem_u32(sm);

    const int b  = blockIdx.y;
    const int i0 = blockIdx.x * 64;
    const int t  = threadIdx.x;
    const int wid  = t >> 5;
    const int lane = t & 31;
    const int g    = lane >> 2;
    const int tid4 = lane & 3;
    const int mq   = wid & 3;           // m-quad: rows mq*16..+15
    const int nq   = (wid >> 2) & 1;    // n-half: cols nq*32..+31
    const int kq   = wid >> 3;          // k-half: k in [kq*32, +32)
    const int m0   = mq * 16;
    const int n0   = nq * 32;

    // tables + bits (once per CTA)
    for (int idx = t; idx < N_; idx += 512) pq2s[idx] = g_pq2[b * N_ + idx];
    {
        const int4 gb = ((const int4*)(g_bits + ((size_t)(b * N_) + i0 + (t >> 3)) * 32))[t & 7];
        *(int4*)(sbits + (t >> 3) * 36 + (t & 7) * 4) = gb;
    }
    float p1r[2], q1r[2];
#pragma unroll
    for (int u = 0; u < 2; u++) {
        const float2 pq = g_pq1[b * N_ + i0 + m0 + u * 8 + g];
        p1r[u] = pq.x; q1r[u] = pq.y;
    }

    // ---- prologue: B(0) ----
    {
        const float4* src = (const float4*)(g_hs + (size_t)(b * 16) * 2048);
        const uint32_t dst = smbase + HS0_OFF;
        CP_ASYNC16(dst + t * 16, src + t);
        CP_ASYNC16(dst + (t + 512) * 16, src + t + 512);
        CP_COMMIT();
    }
    CP_WAIT0();
    __syncthreads();

    float acc[4][4];
#pragma unroll
    for (int nf = 0; nf < 4; nf++)
#pragma unroll
        for (int c = 0; c < 4; c++) acc[nf][c] = 0.f;
    float zac[2] = {0.f, 0.f};

    const int rbit0 = (m0 + g) * 36;
    const int rbit1 = (m0 + 8 + g) * 36;

    for (int tile = 0; tile < 16; tile++) {
        const int cur = tile & 1;
        const float2* hs_ = (const float2*)(sm + (cur ? HS1_OFF : HS0_OFF));

        // issue next h tile
        if (tile < 15) {
            const float4* src = (const float4*)(g_hs + (size_t)(b * 16 + tile + 1) * 2048);
            const uint32_t dst = smbase + (cur ? HS0_OFF : HS1_OFF);
            CP_ASYNC16(dst + t * 16, src + t);
            CP_ASYNC16(dst + (t + 512) * 16, src + t + 512);
            CP_COMMIT();
        }

        // bit words for this warp's 2 rows (kq selects 32-bit word)
        const int wix = tile * 2 + kq;
        const uint32_t word0 = sbits[rbit0 + wix];
        const uint32_t word1 = sbits[rbit1 + wix];

        // ---- MMA: 4 k-steps; A generated per step in fragment layout ----
#pragma unroll
        for (int s = 0; s < 4; s++) {
            const int kk = kq * 32 + s * 8;
            const float2 pqa = pq2s[tile * 64 + kk + tid4];
            const float2 pqb = pq2s[tile * 64 + kk + tid4 + 4];
            const int ba  = s * 8 + tid4;
            const int bb_ = ba + 4;

            float w0 = ((word0 >> ba) & 1u)
                           ? fmaxf(p1r[0] * pqa.x, q1r[0] * pqa.y) : 0.f;
            float w1 = ((word1 >> ba) & 1u)
                           ? fmaxf(p1r[1] * pqa.x, q1r[1] * pqa.y) : 0.f;
            float w2 = ((word0 >> bb_) & 1u)
                           ? fmaxf(p1r[0] * pqb.x, q1r[0] * pqb.y) : 0.f;
            float w3 = ((word1 >> bb_) & 1u)
                           ? fmaxf(p1r[1] * pqb.x, q1r[1] * pqb.y) : 0.f;
            if (nq == 0) {           // z counted once (gen duplicated over nq)
                zac[0] += w0 + w2;
                zac[1] += w1 + w3;
            }
            uint32_t A[4];
            A[0] = __float_as_uint(to_tf32(w0));
            A[1] = __float_as_uint(to_tf32(w1));
            A[2] = __float_as_uint(to_tf32(w2));
            A[3] = __float_as_uint(to_tf32(w3));

            const float2* bp = hs_ + (kq * 4 + s) * 256 + lane;
#pragma unroll
            for (int nf = 0; nf < 4; nf++) {
                const float2 bb = bp[(nq * 4 + nf) * 32];
                mma_tf32(acc[nf], A, __float_as_uint(bb.x), __float_as_uint(bb.y));
            }
        }

        CP_WAIT0();
        __syncthreads();
    }

    // ---- z: quad shfl-reduce (tid4) then per-kq slots (nq==0 only) ----
#pragma unroll
    for (int u = 0; u < 2; u++) {
        zac[u] += __shfl_xor_sync(0xffffffffu, zac[u], 1);
        zac[u] += __shfl_xor_sync(0xffffffffu, zac[u], 2);
    }
    if (nq == 0 && tid4 == 0) {
#pragma unroll
        for (int u = 0; u < 2; u++)
            zp[kq * 64 + m0 + u * 8 + g] = zac[u];
    }
    __syncthreads();
    if (t < 64) zs[t] = zp[t] + zp[64 + t];

    // ---- k-reduction across the 2 kq groups into accbuf ----
#pragma unroll
    for (int ph = 0; ph < 2; ph++) {
        __syncthreads();
        if (kq == ph) {
            const int rA = m0 + g;
#pragma unroll
            for (int nf = 0; nf < 4; nf++) {
                const int cc = n0 + nf * 8 + 2 * tid4;
                float2* pA = (float2*)(accbuf + rA * 72 + cc);
                float2* pB = (float2*)(accbuf + (rA + 8) * 72 + cc);
                if (ph == 0) {
                    *pA = make_float2(acc[nf][0], acc[nf][1]);
                    *pB = make_float2(acc[nf][2], acc[nf][3]);
                } else {
                    float2 vA = *pA, vB = *pB;
                    vA.x += acc[nf][0]; vA.y += acc[nf][1];
                    vB.x += acc[nf][2]; vB.y += acc[nf][3];
                    *pA = vA; *pB = vB;
                }
            }
        }
    }
    __syncthreads();

    // ---- final: normalize + ELU + store (8 elems/thread) ----
    {
        const int row = t >> 3;
        const int c0  = (t & 7) * 8;
        const float inv = 1.f / zs[row];
        const float* src = accbuf + row * 72 + c0;
        float4* op = (float4*)(out + ((size_t)(b * N_ + i0 + row)) * FO + c0);
#pragma unroll
        for (int q = 0; q < 2; q++) {
            float4 x = *(const float4*)(src + 4 * q);
            float4 r;
            float v;
            v = x.x * inv; r.x = (v > 0.f) ? v : expm1f(v);
            v = x.y * inv; r.y = (v > 0.f) ? v : expm1f(v);
            v = x.z * inv; r.z = (v > 0.f) ? v : expm1f(v);
            v = x.w * inv; r.w = (v > 0.f) ? v : expm1f(v);
            op[q] = r;
        }
    }
}

// ---------------------------------------------------------------------------
extern "C" void kernel_launch(void* const* d_in, const int* in_sizes, int n_in,
                              void* d_out, int out_size) {
    const float* inp = (const float*)d_in[0];   // (16,1024,128) f32
    const int*   adj = (const int*)d_in[1];     // (16,1024,1024) i32
    const float* W   = (const float*)d_in[2];   // (128,64) f32
    const float* a   = (const float*)d_in[3];   // (128,1) f32
    float* out = (float*)d_out;                 // (16,1024,64) f32

    static int init = 0;
    if (!init) {
        cudaFuncSetAttribute(k_h_gemm, cudaFuncAttributeMaxDynamicSharedMemorySize,
                             SMEM_HG);
        cudaFuncSetAttribute(k_attn, cudaFuncAttributeMaxDynamicSharedMemorySize,
                             SMEM_ATTN);
        init = 1;
    }

    k_h_gemm<<<dim3(16 + 128, B_), 256, SMEM_HG>>>(inp, W, a, adj);
    k_attn<<<dim3(N_ / 64, B_), 512, SMEM_ATTN>>>(out);
}

// round 16
// speedup vs baseline: 1.0910x; 1.0910x over previous
#include <cuda_runtime.h>
#include <cuda_bf16.h>
#include <math.h>
#include <stdint.h>

#define B_  16
#define N_  1024
#define FIN 128
#define FO  64
#define ALPHA_ 0.2f

// Scratch (device globals: no allocation allowed)
__device__ float2   g_hs[B_ * 16 * 2048];     // tf32 h, B-fragment order, 4 MB
__device__ float2   g_pq1[B_ * N_];           // {exp(s1), exp(a*s1)}
__device__ float2   g_pq2[B_ * N_];           // {exp(s2), exp(a*s2)}
__device__ uint32_t g_bits[B_ * N_ * 32];     // adj bitmask [b][row][word], 2 MB

__device__ __forceinline__ float to_tf32(float x) {
    float r;
    asm("cvt.rna.tf32.f32 %0, %1;" : "=f"(r) : "f"(x));
    return r;
}
__device__ __forceinline__ void mma_tf32(float* d, const uint32_t* a,
                                         uint32_t b0, uint32_t b1) {
    asm volatile(
        "mma.sync.aligned.m16n8k8.row.col.f32.tf32.tf32.f32 "
        "{%0,%1,%2,%3}, {%4,%5,%6,%7}, {%8,%9}, {%0,%1,%2,%3};"
        : "+f"(d[0]), "+f"(d[1]), "+f"(d[2]), "+f"(d[3])
        : "r"(a[0]), "r"(a[1]), "r"(a[2]), "r"(a[3]), "r"(b0), "r"(b1));
}
__device__ __forceinline__ uint32_t smem_u32(const void* p) {
    uint32_t a;
    asm("{ .reg .u64 t; cvta.to.shared.u64 t, %1; cvt.u32.u64 %0, t; }"
        : "=r"(a) : "l"(p));
    return a;
}
#define CP_ASYNC16(dst_u32, src_ptr) \
    asm volatile("cp.async.cg.shared.global [%0], [%1], 16;" \
                 :: "r"(dst_u32), "l"(src_ptr))
#define CP_COMMIT() asm volatile("cp.async.commit_group;" ::: "memory")
#define CP_WAIT0()  asm volatile("cp.async.wait_group 0;" ::: "memory")

// k_attn smem layout (bytes). accbuf[64][72] (18432 B) overlays HS0+HS1.
#define HS0_OFF   0          // float2 hs[2048] = 16384
#define HS1_OFF   16384
#define SBITS_OFF 32768      // uint32 sbits[64][36] = 9216
#define PQ2_OFF   41984      // float2 pq2s[1024] = 8192
#define ZP_OFF    50176      // float zp[4][64] = 1024
#define ZS_OFF    51200      // float zs[64] = 256
#define SMEM_ATTN 51456

#define SMEM_HG   66048      // sI 32K + sW 32K + sA 512 (sT reuses sI)

// ---------------------------------------------------------------------------
// Kernel 1 (fused): blocks x<16: h = inp@W -> g_hs + scores;
//                   blocks x>=16: pack adj -> g_bits (MLP=32, DRAM-bound).
// ---------------------------------------------------------------------------
__global__ __launch_bounds__(256) void k_h_gemm(const float* __restrict__ inp,
                                                const float* __restrict__ W,
                                                const float* __restrict__ a,
                                                const int* __restrict__ adj) {
    extern __shared__ char sm1[];
    const int b  = blockIdx.y;
    const int t  = threadIdx.x;

    if (blockIdx.x >= 16) {
        // ---- adj packing: 8 warps, 1 row/warp; ALL 32 LDGs in flight ----
        const int px   = blockIdx.x - 16;       // 0..127
        const int wid  = t >> 5;
        const int lane = t & 31;
        const int row  = px * 8 + wid;
        const int* ap = adj + (size_t)b * N_ * N_ + (size_t)row * N_ + lane;
        uint32_t* bp = g_bits + ((size_t)b * N_ + row) * 32;
        int va[32];
#pragma unroll
        for (int j = 0; j < 32; j++) va[j] = ap[j * 32];
#pragma unroll
        for (int j = 0; j < 32; j++) {
            const uint32_t msk = __ballot_sync(0xffffffffu, va[j] > 0);
            if (lane == 0) bp[j] = msk;
        }
        return;
    }

    // ---- h-gemm part ----
    float* sI = (float*)sm1;             // [64][128]
    float* sW = (float*)(sm1 + 32768);   // [128][64]
    float* sA = (float*)(sm1 + 65536);   // [128]
    float* sT = (float*)sm1;             // [64][68] transpose stage (reuses sI)

    const int bx   = blockIdx.x;         // tile index (64 rows per tile)
    const int row0 = bx * 64;

#pragma unroll
    for (int k = 0; k < 8; k++)
        ((float4*)sW)[t + k * 256] = ((const float4*)W)[t + k * 256];
    const float4* ip = (const float4*)(inp + ((size_t)b * N_ + row0) * FIN);
#pragma unroll
    for (int k = 0; k < 8; k++)
        ((float4*)sI)[t + k * 256] = ip[t + k * 256];
    if (t < 128) sA[t] = a[t];
    __syncthreads();

    const int ot = t & 15;
    const int rt = t >> 4;
    const int lane = t & 31;

    float acc[4][4];
#pragma unroll
    for (int r = 0; r < 4; r++)
#pragma unroll
        for (int c = 0; c < 4; c++) acc[r][c] = 0.f;

#pragma unroll 4
    for (int k = 0; k < FIN; k++) {
        const float4 w4 = *(const float4*)(sW + k * FO + ot * 4);
#pragma unroll
        for (int r = 0; r < 4; r++) {
            const float iv = sI[(rt * 4 + r) * FIN + k];
            acc[r][0] += iv * w4.x;
            acc[r][1] += iv * w4.y;
            acc[r][2] += iv * w4.z;
            acc[r][3] += iv * w4.w;
        }
    }

    // fused scores
    float s1p[4], s2p[4];
#pragma unroll
    for (int r = 0; r < 4; r++) {
        float v1 = 0.f, v2 = 0.f;
#pragma unroll
        for (int c = 0; c < 4; c++) {
            v1 += acc[r][c] * sA[ot * 4 + c];
            v2 += acc[r][c] * sA[64 + ot * 4 + c];
        }
        s1p[r] = v1; s2p[r] = v2;
    }
#pragma unroll
    for (int off = 8; off > 0; off >>= 1) {
#pragma unroll
        for (int r = 0; r < 4; r++) {
            s1p[r] += __shfl_xor_sync(0xffffffffu, s1p[r], off);
            s2p[r] += __shfl_xor_sync(0xffffffffu, s2p[r], off);
        }
    }

    // stage tf32 h into sT (stride 68), then write fragment-ordered g_hs
    __syncthreads();   // done reading sI
#pragma unroll
    for (int r = 0; r < 4; r++) {
        float4 wq;
        wq.x = to_tf32(acc[r][0]);
        wq.y = to_tf32(acc[r][1]);
        wq.z = to_tf32(acc[r][2]);
        wq.w = to_tf32(acc[r][3]);
        *(float4*)(sT + (rt * 4 + r) * 68 + ot * 4) = wq;
    }
    __syncthreads();

    {
        float2* dst = g_hs + (size_t)(b * 16 + bx) * 2048;
#pragma unroll
        for (int q = 0; q < 8; q++) {
            const int f   = q * 256 + t;
            const int l   = f & 31;
            const int blk = f >> 5;          // koct*8 + nf
            const int j0  = (blk >> 3) * 8 + (l & 3);
            const int c   = (blk & 7) * 8 + (l >> 2);
            float2 v;
            v.x = sT[j0 * 68 + c];
            v.y = sT[(j0 + 4) * 68 + c];
            dst[f] = v;
        }
    }

    if ((lane & 15) == 0) {
#pragma unroll
        for (int r = 0; r < 4; r++) {
            const int gi = b * N_ + row0 + rt * 4 + r;
            g_pq1[gi] = make_float2(__expf(s1p[r]), __expf(ALPHA_ * s1p[r]));
            g_pq2[gi] = make_float2(__expf(s2p[r]), __expf(ALPHA_ * s2p[r]));
        }
    }
}

// ---------------------------------------------------------------------------
// Kernel 2: attention via mma.sync tf32; A generated in registers from
// pre-packed bitmasks, B pre-fragmented (LDS.64).
// CTA: 64 i x 64 o, 512 thr, 16 warps = 4m x 4k (n UNSPLIT -> no gen dup),
// warp tile 16m x 64n x 16k, acc 32 regs.
// ---------------------------------------------------------------------------
__global__ __launch_bounds__(512, 2) void k_attn(float* __restrict__ out) {
    extern __shared__ char sm[];
    uint32_t* sbits = (uint32_t*)(sm + SBITS_OFF);  // [64][36]
    float2*   pq2s = (float2*)(sm + PQ2_OFF);
    float*    zp   = (float*)(sm + ZP_OFF);     // [4][64]
    float*    zs   = (float*)(sm + ZS_OFF);     // [64]
    float*    accbuf = (float*)sm;              // [64][72] (reuse after loop)
    const uint32_t smbase = smem_u32(sm);

    const int b  = blockIdx.y;
    const int i0 = blockIdx.x * 64;
    const int t  = threadIdx.x;
    const int wid  = t >> 5;
    const int lane = t & 31;
    const int g    = lane >> 2;
    const int tid4 = lane & 3;
    const int mq   = wid & 3;           // m-quad: rows mq*16..+15
    const int kq   = wid >> 2;          // k-quarter: k in [kq*16, +16)
    const int m0   = mq * 16;

    // tables + bits (once per CTA)
    for (int idx = t; idx < N_; idx += 512) pq2s[idx] = g_pq2[b * N_ + idx];
    {
        const int4 gb = ((const int4*)(g_bits + ((size_t)(b * N_) + i0 + (t >> 3)) * 32))[t & 7];
        *(int4*)(sbits + (t >> 3) * 36 + (t & 7) * 4) = gb;
    }
    float p1r[2], q1r[2];
#pragma unroll
    for (int u = 0; u < 2; u++) {
        const float2 pq = g_pq1[b * N_ + i0 + m0 + u * 8 + g];
        p1r[u] = pq.x; q1r[u] = pq.y;
    }

    // ---- prologue: B(0) ----
    {
        const float4* src = (const float4*)(g_hs + (size_t)(b * 16) * 2048);
        const uint32_t dst = smbase + HS0_OFF;
        CP_ASYNC16(dst + t * 16, src + t);
        CP_ASYNC16(dst + (t + 512) * 16, src + t + 512);
        CP_COMMIT();
    }
    CP_WAIT0();
    __syncthreads();

    float acc[8][4];
#pragma unroll
    for (int nf = 0; nf < 8; nf++)
#pragma unroll
        for (int c = 0; c < 4; c++) acc[nf][c] = 0.f;
    float zac[2] = {0.f, 0.f};

    const int rbit0 = (m0 + g) * 36;
    const int rbit1 = (m0 + 8 + g) * 36;
    const int bitb  = (kq & 1) * 16;    // bit window within the 32-bit word

    for (int tile = 0; tile < 16; tile++) {
        const int cur = tile & 1;
        const float2* hs_ = (const float2*)(sm + (cur ? HS1_OFF : HS0_OFF));

        // issue next h tile
        if (tile < 15) {
            const float4* src = (const float4*)(g_hs + (size_t)(b * 16 + tile + 1) * 2048);
            const uint32_t dst = smbase + (cur ? HS0_OFF : HS1_OFF);
            CP_ASYNC16(dst + t * 16, src + t);
            CP_ASYNC16(dst + (t + 512) * 16, src + t + 512);
            CP_COMMIT();
        }

        // bit words for this warp's 2 rows
        const int wix = tile * 2 + (kq >> 1);
        const uint32_t word0 = sbits[rbit0 + wix];
        const uint32_t word1 = sbits[rbit1 + wix];

        // ---- MMA: 2 k-steps; A generated per step (NO duplication) ----
#pragma unroll
        for (int s = 0; s < 2; s++) {
            const int kk = kq * 16 + s * 8;
            const float2 pqa = pq2s[tile * 64 + kk + tid4];
            const float2 pqb = pq2s[tile * 64 + kk + tid4 + 4];
            const int ba  = bitb + s * 8 + tid4;
            const int bb_ = ba + 4;

            float w0 = ((word0 >> ba) & 1u)
                           ? fmaxf(p1r[0] * pqa.x, q1r[0] * pqa.y) : 0.f;
            float w1 = ((word1 >> ba) & 1u)
                           ? fmaxf(p1r[1] * pqa.x, q1r[1] * pqa.y) : 0.f;
            float w2 = ((word0 >> bb_) & 1u)
                           ? fmaxf(p1r[0] * pqb.x, q1r[0] * pqb.y) : 0.f;
            float w3 = ((word1 >> bb_) & 1u)
                           ? fmaxf(p1r[1] * pqb.x, q1r[1] * pqb.y) : 0.f;
            zac[0] += w0 + w2;
            zac[1] += w1 + w3;
            uint32_t A[4];
            A[0] = __float_as_uint(to_tf32(w0));
            A[1] = __float_as_uint(to_tf32(w1));
            A[2] = __float_as_uint(to_tf32(w2));
            A[3] = __float_as_uint(to_tf32(w3));

            const float2* bp = hs_ + (kq * 2 + s) * 256 + lane;
#pragma unroll
            for (int nf = 0; nf < 8; nf++) {
                const float2 bb = bp[nf * 32];
                mma_tf32(acc[nf], A, __float_as_uint(bb.x), __float_as_uint(bb.y));
            }
        }

        CP_WAIT0();
        __syncthreads();
    }

    // ---- z: quad shfl-reduce (tid4) then per-kq slots ----
#pragma unroll
    for (int u = 0; u < 2; u++) {
        zac[u] += __shfl_xor_sync(0xffffffffu, zac[u], 1);
        zac[u] += __shfl_xor_sync(0xffffffffu, zac[u], 2);
    }
    if (tid4 == 0) {
#pragma unroll
        for (int u = 0; u < 2; u++)
            zp[kq * 64 + m0 + u * 8 + g] = zac[u];
    }
    __syncthreads();
    if (t < 64) zs[t] = (zp[t] + zp[64 + t]) + (zp[128 + t] + zp[192 + t]);

    // ---- k-reduction across the 4 kq groups into accbuf ----
#pragma unroll
    for (int ph = 0; ph < 4; ph++) {
        __syncthreads();
        if (kq == ph) {
            const int rA = m0 + g;
#pragma unroll
            for (int nf = 0; nf < 8; nf++) {
                const int cc = nf * 8 + 2 * tid4;
                float2* pA = (float2*)(accbuf + rA * 72 + cc);
                float2* pB = (float2*)(accbuf + (rA + 8) * 72 + cc);
                if (ph == 0) {
                    *pA = make_float2(acc[nf][0], acc[nf][1]);
                    *pB = make_float2(acc[nf][2], acc[nf][3]);
                } else {
                    float2 vA = *pA, vB = *pB;
                    vA.x += acc[nf][0]; vA.y += acc[nf][1];
                    vB.x += acc[nf][2]; vB.y += acc[nf][3];
                    *pA = vA; *pB = vB;
                }
            }
        }
    }
    __syncthreads();

    // ---- final: normalize + ELU + store (8 elems/thread) ----
    {
        const int row = t >> 3;
        const int c0  = (t & 7) * 8;
        const float inv = 1.f / zs[row];
        const float* src = accbuf + row * 72 + c0;
        float4* op = (float4*)(out + ((size_t)(b * N_ + i0 + row)) * FO + c0);
#pragma unroll
        for (int q = 0; q < 2; q++) {
            float4 x = *(const float4*)(src + 4 * q);
            float4 r;
            float v;
            v = x.x * inv; r.x = (v > 0.f) ? v : expm1f(v);
            v = x.y * inv; r.y = (v > 0.f) ? v : expm1f(v);
            v = x.z * inv; r.z = (v > 0.f) ? v : expm1f(v);
            v = x.w * inv; r.w = (v > 0.f) ? v : expm1f(v);
            op[q] = r;
        }
    }
}

// ---------------------------------------------------------------------------
extern "C" void kernel_launch(void* const* d_in, const int* in_sizes, int n_in,
                              void* d_out, int out_size) {
    const float* inp = (const float*)d_in[0];   // (16,1024,128) f32
    const int*   adj = (const int*)d_in[1];     // (16,1024,1024) i32
    const float* W   = (const float*)d_in[2];   // (128,64) f32
    const float* a   = (const float*)d_in[3];   // (128,1) f32
    float* out = (float*)d_out;                 // (16,1024,64) f32

    static int init = 0;
    if (!init) {
        cudaFuncSetAttribute(k_h_gemm, cudaFuncAttributeMaxDynamicSharedMemorySize,
                             SMEM_HG);
        cudaFuncSetAttribute(k_attn, cudaFuncAttributeMaxDynamicSharedMemorySize,
                             SMEM_ATTN);
        init = 1;
    }

    k_h_gemm<<<dim3(16 + 128, B_), 256, SMEM_HG>>>(inp, W, a, adj);
    k_attn<<<dim3(N_ / 64, B_), 512, SMEM_ATTN>>>(out);
}

// round 17
// speedup vs baseline: 1.1454x; 1.0499x over previous
#include <cuda_runtime.h>
#include <cuda_bf16.h>
#include <math.h>
#include <stdint.h>

#define B_  16
#define N_  1024
#define FIN 128
#define FO  64
#define ALPHA_ 0.2f

// Scratch (device globals: no allocation allowed)
__device__ float2 g_hs[B_ * 16 * 2048];       // tf32 h, B-fragment order, 4 MB
__device__ float2 g_pq1[B_ * N_];             // {exp(s1), exp(a*s1)}
__device__ float2 g_pq2[B_ * N_];             // {exp(s2), exp(a*s2)}

__device__ __forceinline__ float to_tf32(float x) {
    float r;
    asm("cvt.rna.tf32.f32 %0, %1;" : "=f"(r) : "f"(x));
    return r;
}
__device__ __forceinline__ void mma_tf32(float* d, const uint32_t* a,
                                         uint32_t b0, uint32_t b1) {
    asm volatile(
        "mma.sync.aligned.m16n8k8.row.col.f32.tf32.tf32.f32 "
        "{%0,%1,%2,%3}, {%4,%5,%6,%7}, {%8,%9}, {%0,%1,%2,%3};"
        : "+f"(d[0]), "+f"(d[1]), "+f"(d[2]), "+f"(d[3])
        : "r"(a[0]), "r"(a[1]), "r"(a[2]), "r"(a[3]), "r"(b0), "r"(b1));
}
__device__ __forceinline__ uint32_t smem_u32(const void* p) {
    uint32_t a;
    asm("{ .reg .u64 t; cvta.to.shared.u64 t, %1; cvt.u32.u64 %0, t; }"
        : "=r"(a) : "l"(p));
    return a;
}
#define CP_ASYNC16(dst_u32, src_ptr) \
    asm volatile("cp.async.cg.shared.global [%0], [%1], 16;" \
                 :: "r"(dst_u32), "l"(src_ptr))
#define CP_COMMIT() asm volatile("cp.async.commit_group;" ::: "memory")
#define CP_WAIT0()  asm volatile("cp.async.wait_group 0;" ::: "memory")

// k_attn smem layout (bytes). accbuf[64][72] (18432 B) overlays HS0+HS1.
#define HS0_OFF   0          // float2 hs[2048] = 16384
#define HS1_OFF   16384
#define SBITS_OFF 32768      // uint32 sbits[64][36] = 9216
#define PQ2_OFF   41984      // float2 pq2s[1024] = 8192
#define ZP_OFF    50176      // float zp[4][64] = 1024
#define ZS_OFF    51200      // float zs[64] = 256
#define SMEM_ATTN 51456

#define SMEM_HG   66048      // sI 32K + sW 32K + sA 512 (sT reuses sI)

// ---------------------------------------------------------------------------
// Kernel 1: h = inp @ W -> g_hs (tf32, B-fragment order) + fused exps.
// ---------------------------------------------------------------------------
__global__ __launch_bounds__(256) void k_h_gemm(const float* __restrict__ inp,
                                                const float* __restrict__ W,
                                                const float* __restrict__ a) {
    extern __shared__ char sm1[];
    float* sI = (float*)sm1;             // [64][128]
    float* sW = (float*)(sm1 + 32768);   // [128][64]
    float* sA = (float*)(sm1 + 65536);   // [128]
    float* sT = (float*)sm1;             // [64][68] transpose stage (reuses sI)

    const int b    = blockIdx.y;
    const int bx   = blockIdx.x;         // tile index (64 rows per tile)
    const int row0 = bx * 64;
    const int t    = threadIdx.x;

#pragma unroll
    for (int k = 0; k < 8; k++)
        ((float4*)sW)[t + k * 256] = ((const float4*)W)[t + k * 256];
    const float4* ip = (const float4*)(inp + ((size_t)b * N_ + row0) * FIN);
#pragma unroll
    for (int k = 0; k < 8; k++)
        ((float4*)sI)[t + k * 256] = ip[t + k * 256];
    if (t < 128) sA[t] = a[t];
    __syncthreads();

    const int ot = t & 15;
    const int rt = t >> 4;
    const int lane = t & 31;

    float acc[4][4];
#pragma unroll
    for (int r = 0; r < 4; r++)
#pragma unroll
        for (int c = 0; c < 4; c++) acc[r][c] = 0.f;

#pragma unroll 4
    for (int k = 0; k < FIN; k++) {
        const float4 w4 = *(const float4*)(sW + k * FO + ot * 4);
#pragma unroll
        for (int r = 0; r < 4; r++) {
            const float iv = sI[(rt * 4 + r) * FIN + k];
            acc[r][0] += iv * w4.x;
            acc[r][1] += iv * w4.y;
            acc[r][2] += iv * w4.z;
            acc[r][3] += iv * w4.w;
        }
    }

    // fused scores
    float s1p[4], s2p[4];
#pragma unroll
    for (int r = 0; r < 4; r++) {
        float v1 = 0.f, v2 = 0.f;
#pragma unroll
        for (int c = 0; c < 4; c++) {
            v1 += acc[r][c] * sA[ot * 4 + c];
            v2 += acc[r][c] * sA[64 + ot * 4 + c];
        }
        s1p[r] = v1; s2p[r] = v2;
    }
#pragma unroll
    for (int off = 8; off > 0; off >>= 1) {
#pragma unroll
        for (int r = 0; r < 4; r++) {
            s1p[r] += __shfl_xor_sync(0xffffffffu, s1p[r], off);
            s2p[r] += __shfl_xor_sync(0xffffffffu, s2p[r], off);
        }
    }

    // stage tf32 h into sT (stride 68), then write fragment-ordered g_hs
    __syncthreads();   // done reading sI
#pragma unroll
    for (int r = 0; r < 4; r++) {
        float4 wq;
        wq.x = to_tf32(acc[r][0]);
        wq.y = to_tf32(acc[r][1]);
        wq.z = to_tf32(acc[r][2]);
        wq.w = to_tf32(acc[r][3]);
        *(float4*)(sT + (rt * 4 + r) * 68 + ot * 4) = wq;
    }
    __syncthreads();

    {
        float2* dst = g_hs + (size_t)(b * 16 + bx) * 2048;
#pragma unroll
        for (int q = 0; q < 8; q++) {
            const int f   = q * 256 + t;
            const int l   = f & 31;
            const int blk = f >> 5;          // koct*8 + nf
            const int j0  = (blk >> 3) * 8 + (l & 3);
            const int c   = (blk & 7) * 8 + (l >> 2);
            float2 v;
            v.x = sT[j0 * 68 + c];
            v.y = sT[(j0 + 4) * 68 + c];
            dst[f] = v;
        }
    }

    if ((lane & 15) == 0) {
#pragma unroll
        for (int r = 0; r < 4; r++) {
            const int gi = b * N_ + row0 + rt * 4 + r;
            g_pq1[gi] = make_float2(__expf(s1p[r]), __expf(ALPHA_ * s1p[r]));
            g_pq2[gi] = make_float2(__expf(s2p[r]), __expf(ALPHA_ * s2p[r]));
        }
    }
}

// ---------------------------------------------------------------------------
// Kernel 2: attention via mma.sync tf32; A generated in registers from
// bitmasks PACKED IN-KERNEL (chunk-ahead: chunk c ready >=4 tiles early),
// B pre-fragmented (LDS.64).
// CTA: 64 i x 64 o, 512 thr, 16 warps = 4m x 4k, warp tile 16m x 64n x 16k.
// ---------------------------------------------------------------------------
__global__ __launch_bounds__(512, 2) void k_attn(const int* __restrict__ adj,
                                                 float* __restrict__ out) {
    extern __shared__ char sm[];
    uint32_t* sbits = (uint32_t*)(sm + SBITS_OFF);  // [64][36]
    float2*   pq2s = (float2*)(sm + PQ2_OFF);
    float*    zp   = (float*)(sm + ZP_OFF);     // [4][64]
    float*    zs   = (float*)(sm + ZS_OFF);     // [64]
    float*    accbuf = (float*)sm;              // [64][72] (reuse after loop)
    const uint32_t smbase = smem_u32(sm);

    const int b  = blockIdx.y;
    const int i0 = blockIdx.x * 64;
    const int t  = threadIdx.x;
    const int wid  = t >> 5;
    const int lane = t & 31;
    const int g    = lane >> 2;
    const int tid4 = lane & 3;
    const int mq   = wid & 3;           // m-quad: rows mq*16..+15
    const int kq   = wid >> 2;          // k-quarter: k in [kq*16, +16)
    const int m0   = mq * 16;

    const int* adjb = adj + (size_t)b * N_ * N_ + (size_t)i0 * N_;

    // ---- chunk-packer: words c*8..c*8+7 for all 64 rows (32 tasks/warp) ----
    // task tid_: row = tid_>>3, word = c*8 + (tid_&7). 8-batch pipelined loads.
#define PACK_CHUNK(c) do {                                                     \
        const int bt = wid * 32;                                               \
        int va[8], vb[8];                                                      \
        _Pragma("unroll")                                                      \
        for (int j = 0; j < 8; j++) {                                          \
            const int td = bt + j;                                             \
            va[j] = adjb[(size_t)(td >> 3) * N_ +                              \
                         ((c) * 8 + (td & 7)) * 32 + lane];                    \
        }                                                                      \
        _Pragma("unroll")                                                      \
        for (int r = 0; r < 4; r++) {                                          \
            if (r < 3) {                                                       \
                _Pragma("unroll")                                              \
                for (int j = 0; j < 8; j++) {                                  \
                    const int td = bt + (r + 1) * 8 + j;                       \
                    vb[j] = adjb[(size_t)(td >> 3) * N_ +                      \
                                 ((c) * 8 + (td & 7)) * 32 + lane];            \
                }                                                              \
            }                                                                  \
            _Pragma("unroll")                                                  \
            for (int j = 0; j < 8; j++) {                                      \
                const int td = bt + r * 8 + j;                                 \
                const uint32_t msk = __ballot_sync(0xffffffffu, va[j] > 0);    \
                if (lane == 0)                                                 \
                    sbits[(td >> 3) * 36 + (c) * 8 + (td & 7)] = msk;          \
            }                                                                  \
            _Pragma("unroll")                                                  \
            for (int j = 0; j < 8; j++) va[j] = vb[j];                         \
        }                                                                      \
    } while (0)

    // tables
    for (int idx = t; idx < N_; idx += 512) pq2s[idx] = g_pq2[b * N_ + idx];
    float p1r[2], q1r[2];
#pragma unroll
    for (int u = 0; u < 2; u++) {
        const float2 pq = g_pq1[b * N_ + i0 + m0 + u * 8 + g];
        p1r[u] = pq.x; q1r[u] = pq.y;
    }

    // ---- prologue: B(0) cp.async first (overlaps pack), then chunk 0 ----
    {
        const float4* src = (const float4*)(g_hs + (size_t)(b * 16) * 2048);
        const uint32_t dst = smbase + HS0_OFF;
        CP_ASYNC16(dst + t * 16, src + t);
        CP_ASYNC16(dst + (t + 512) * 16, src + t + 512);
        CP_COMMIT();
    }
    PACK_CHUNK(0);
    CP_WAIT0();
    __syncthreads();

    float acc[8][4];
#pragma unroll
    for (int nf = 0; nf < 8; nf++)
#pragma unroll
        for (int c = 0; c < 4; c++) acc[nf][c] = 0.f;
    float zac[2] = {0.f, 0.f};

    const int rbit0 = (m0 + g) * 36;
    const int rbit1 = (m0 + 8 + g) * 36;
    const int bitb  = (kq & 1) * 16;    // bit window within the 32-bit word

    for (int tile = 0; tile < 16; tile++) {
        const int cur = tile & 1;
        const float2* hs_ = (const float2*)(sm + (cur ? HS1_OFF : HS0_OFF));

        // issue next h tile
        if (tile < 15) {
            const float4* src = (const float4*)(g_hs + (size_t)(b * 16 + tile + 1) * 2048);
            const uint32_t dst = smbase + (cur ? HS0_OFF : HS1_OFF);
            CP_ASYNC16(dst + t * 16, src + t);
            CP_ASYNC16(dst + (t + 512) * 16, src + t + 512);
            CP_COMMIT();
        }

        // bit words for this warp's 2 rows
        const int wix = tile * 2 + (kq >> 1);
        const uint32_t word0 = sbits[rbit0 + wix];
        const uint32_t word1 = sbits[rbit1 + wix];

        // ---- MMA: 2 k-steps; A generated per step (no duplication) ----
#pragma unroll
        for (int s = 0; s < 2; s++) {
            const int kk = kq * 16 + s * 8;
            const float2 pqa = pq2s[tile * 64 + kk + tid4];
            const float2 pqb = pq2s[tile * 64 + kk + tid4 + 4];
            const int ba  = bitb + s * 8 + tid4;
            const int bb_ = ba + 4;

            float w0 = ((word0 >> ba) & 1u)
                           ? fmaxf(p1r[0] * pqa.x, q1r[0] * pqa.y) : 0.f;
            float w1 = ((word1 >> ba) & 1u)
                           ? fmaxf(p1r[1] * pqa.x, q1r[1] * pqa.y) : 0.f;
            float w2 = ((word0 >> bb_) & 1u)
                           ? fmaxf(p1r[0] * pqb.x, q1r[0] * pqb.y) : 0.f;
            float w3 = ((word1 >> bb_) & 1u)
                           ? fmaxf(p1r[1] * pqb.x, q1r[1] * pqb.y) : 0.f;
            zac[0] += w0 + w2;
            zac[1] += w1 + w3;
            uint32_t A[4];
            A[0] = __float_as_uint(to_tf32(w0));
            A[1] = __float_as_uint(to_tf32(w1));
            A[2] = __float_as_uint(to_tf32(w2));
            A[3] = __float_as_uint(to_tf32(w3));

            const float2* bp = hs_ + (kq * 2 + s) * 256 + lane;
#pragma unroll
            for (int nf = 0; nf < 8; nf++) {
                const float2 bb = bp[nf * 32];
                mma_tf32(acc[nf], A, __float_as_uint(bb.x), __float_as_uint(bb.y));
            }
        }

        // ---- chunk-ahead adj packing (chunk c ready >=4 tiles early) ----
        if (tile == 0)      PACK_CHUNK(1);
        else if (tile == 4) PACK_CHUNK(2);
        else if (tile == 8) PACK_CHUNK(3);

        CP_WAIT0();
        __syncthreads();
    }

    // ---- z: quad shfl-reduce (tid4) then per-kq slots ----
#pragma unroll
    for (int u = 0; u < 2; u++) {
        zac[u] += __shfl_xor_sync(0xffffffffu, zac[u], 1);
        zac[u] += __shfl_xor_sync(0xffffffffu, zac[u], 2);
    }
    if (tid4 == 0) {
#pragma unroll
        for (int u = 0; u < 2; u++)
            zp[kq * 64 + m0 + u * 8 + g] = zac[u];
    }
    __syncthreads();
    if (t < 64) zs[t] = (zp[t] + zp[64 + t]) + (zp[128 + t] + zp[192 + t]);

    // ---- k-reduction across the 4 kq groups into accbuf ----
#pragma unroll
    for (int ph = 0; ph < 4; ph++) {
        __syncthreads();
        if (kq == ph) {
            const int rA = m0 + g;
#pragma unroll
            for (int nf = 0; nf < 8; nf++) {
                const int cc = nf * 8 + 2 * tid4;
                float2* pA = (float2*)(accbuf + rA * 72 + cc);
                float2* pB = (float2*)(accbuf + (rA + 8) * 72 + cc);
                if (ph == 0) {
                    *pA = make_float2(acc[nf][0], acc[nf][1]);
                    *pB = make_float2(acc[nf][2], acc[nf][3]);
                } else {
                    float2 vA = *pA, vB = *pB;
                    vA.x += acc[nf][0]; vA.y += acc[nf][1];
                    vB.x += acc[nf][2]; vB.y += acc[nf][3];
                    *pA = vA; *pB = vB;
                }
            }
        }
    }
    __syncthreads();

    // ---- final: normalize + ELU + store (8 elems/thread) ----
    {
        const int row = t >> 3;
        const int c0  = (t & 7) * 8;
        const float inv = 1.f / zs[row];
        const float* src = accbuf + row * 72 + c0;
        float4* op = (float4*)(out + ((size_t)(b * N_ + i0 + row)) * FO + c0);
#pragma unroll
        for (int q = 0; q < 2; q++) {
            float4 x = *(const float4*)(src + 4 * q);
            float4 r;
            float v;
            v = x.x * inv; r.x = (v > 0.f) ? v : expm1f(v);
            v = x.y * inv; r.y = (v > 0.f) ? v : expm1f(v);
            v = x.z * inv; r.z = (v > 0.f) ? v : expm1f(v);
            v = x.w * inv; r.w = (v > 0.f) ? v : expm1f(v);
            op[q] = r;
        }
    }
}

// ---------------------------------------------------------------------------
extern "C" void kernel_launch(void* const* d_in, const int* in_sizes, int n_in,
                              void* d_out, int out_size) {
    const float* inp = (const float*)d_in[0];   // (16,1024,128) f32
    const int*   adj = (const int*)d_in[1];     // (16,1024,1024) i32
    const float* W   = (const float*)d_in[2];   // (128,64) f32
    const float* a   = (const float*)d_in[3];   // (128,1) f32
    float* out = (float*)d_out;                 // (16,1024,64) f32

    static int init = 0;
    if (!init) {
        cudaFuncSetAttribute(k_h_gemm, cudaFuncAttributeMaxDynamicSharedMemorySize,
                             SMEM_HG);
        cudaFuncSetAttribute(k_attn, cudaFuncAttributeMaxDynamicSharedMemorySize,
                             SMEM_ATTN);
        init = 1;
    }

    k_h_gemm<<<dim3(N_ / 64, B_), 256, SMEM_HG>>>(inp, W, a);
    k_attn<<<dim3(N_ / 64, B_), 512, SMEM_ATTN>>>(adj, out);
}